// round 16
// baseline (speedup 1.0000x reference)
#include <cuda_runtime.h>
#include <cstdint>

// LIF recurrence — FINAL kernel (roofline-bound, 6-run stable at 36.90-36.99us).
// x: [B*N, T] fp32, T=100 contiguous.
//   u_t = decay*u_{t-1} + x_t - o_{t-1}*VTH ; o_t = (u_t - VTH > 0) ? 1 : 0
//
// Wall time is a flat floor set by compulsory DRAM traffic: 105MB read +
// 105MB write per replay at ~5.7TB/s effective mixed-R/W bandwidth
// (~71% of 8TB/s pure-read spec) => ~36.9us. Established by:
//  - 7 architectures (flat LDG, smem-staged, double-buffered pipeline,
//    persistent, warp-specialized TMA ring, block-shared tile) converge
//    at 36.9-41.0us wall while ncu kernel time varies 28-35.5us;
//  - 3 L2-residency mechanisms (TMA cache_hint, st.cs, cp.async
//    cache_hint) all exact no-ops; input not pinnable across replays.
//
// Geometry: per-warp 64-row tile = 25600B contiguous gmem span.
//  Phase 1: whole tile as one cp.async (LDGSTS.128) burst - fully
//           coalesced, 25.6KB in flight per warp.
//  Phase 2: 2 interleaved recurrence chains per thread (rows lane,
//           lane+32), conflict-free LDS.128/STS.128, spikes overwrite
//           input in place.
//  Phase 3: coalesced st.global.cs.v4 streaming stores.
// 2 warps/block, 51.2KB smem, grid 2048 (~3.4 waves on 152 SMs).

#define VTH 0.5f
#define T_STEPS 100
#define T_VEC (T_STEPS / 4)                    // 25
#define ROWS_PER_TILE 64
#define TILE_FLOATS (ROWS_PER_TILE * T_STEPS)  // 6400 floats = 25600 B
#define TILE_VEC (TILE_FLOATS / 4)             // 1600 float4
#define VEC_PER_LANE (TILE_VEC / 32)           // 50
#define WARPS_PER_BLOCK 2
#define BLOCK_THREADS (WARPS_PER_BLOCK * 32)
#define SMEM_BYTES (WARPS_PER_BLOCK * TILE_FLOATS * sizeof(float))  // 51200

__device__ __forceinline__ void cp_async16(uint32_t smem_dst, const void* gmem_src) {
    asm volatile("cp.async.cg.shared.global [%0], [%1], 16;\n"
                 :: "r"(smem_dst), "l"(gmem_src));
}
__device__ __forceinline__ void cp_async_commit() {
    asm volatile("cp.async.commit_group;\n" ::: "memory");
}
__device__ __forceinline__ void cp_async_wait_0() {
    asm volatile("cp.async.wait_group 0;\n" ::: "memory");
}
__device__ __forceinline__ void stg_cs_128(float4* p, float4 v) {
    asm volatile("st.global.cs.v4.f32 [%0], {%1, %2, %3, %4};"
                 :: "l"(p), "f"(v.x), "f"(v.y), "f"(v.z), "f"(v.w) : "memory");
}

#define LIF_STEP(u, o, xv)                      \
    do {                                        \
        u = fmaf(decay, u, xv);                 \
        u = fmaf(-VTH, o, u);                   \
        o = (u > VTH) ? 1.0f : 0.0f;            \
    } while (0)

__global__ void __launch_bounds__(BLOCK_THREADS) lif_kernel(
    const float* __restrict__ x,
    const float* __restrict__ decay_p,
    float* __restrict__ out,
    int n_neurons)
{
    extern __shared__ float smem[];

    const int warp = threadIdx.x >> 5;
    const int lane = threadIdx.x & 31;

    const int ntiles = n_neurons / ROWS_PER_TILE;          // 4096
    const int t = blockIdx.x * WARPS_PER_BLOCK + warp;
    if (t >= ntiles) return;

    const float decay = __ldg(decay_p);

    float* buf = smem + (size_t)warp * TILE_FLOATS;
    uint32_t buf_s = (uint32_t)__cvta_generic_to_shared(buf);

    // ---- Phase 1: whole 25.6KB tile via cp.async, all in flight at once ----
    const float4* g = reinterpret_cast<const float4*>(x + (size_t)t * TILE_FLOATS);
#pragma unroll
    for (int i = 0; i < VEC_PER_LANE; ++i) {
        int idx = lane + 32 * i;                           // coalesced span
        cp_async16(buf_s + (uint32_t)idx * 16u, g + idx);
    }
    cp_async_commit();
    cp_async_wait_0();
    __syncwarp();

    // ---- Phase 2: two interleaved chains per thread (rows lane, lane+32) ----
    {
        float4* r0 = reinterpret_cast<float4*>(buf + (size_t)lane * T_STEPS);
        float4* r1 = reinterpret_cast<float4*>(buf + (size_t)(lane + 32) * T_STEPS);

        float u0 = 0.0f, o0 = 0.0f;
        float u1 = 0.0f, o1 = 0.0f;
#pragma unroll
        for (int q = 0; q < T_VEC; ++q) {
            float4 a = r0[q];
            float4 b = r1[q];
            float4 oa, ob;

            LIF_STEP(u0, o0, a.x);  oa.x = o0;
            LIF_STEP(u1, o1, b.x);  ob.x = o1;
            LIF_STEP(u0, o0, a.y);  oa.y = o0;
            LIF_STEP(u1, o1, b.y);  ob.y = o1;
            LIF_STEP(u0, o0, a.z);  oa.z = o0;
            LIF_STEP(u1, o1, b.z);  ob.z = o1;
            LIF_STEP(u0, o0, a.w);  oa.w = o0;
            LIF_STEP(u1, o1, b.w);  ob.w = o1;

            r0[q] = oa;              // spikes overwrite consumed input
            r1[q] = ob;
        }
    }
    __syncwarp();

    // ---- Phase 3: coalesced streaming stores ----
    {
        const float4* c4 = reinterpret_cast<const float4*>(buf);
        float4* go = reinterpret_cast<float4*>(out + (size_t)t * TILE_FLOATS);
#pragma unroll
        for (int i = 0; i < VEC_PER_LANE; ++i) {
            int idx = lane + 32 * i;
            stg_cs_128(go + idx, c4[idx]);
        }
    }
}

extern "C" void kernel_launch(void* const* d_in, const int* in_sizes, int n_in,
                              void* d_out, int out_size)
{
    const float* x       = (const float*)d_in[0];
    const float* decay_p = (const float*)d_in[1];
    float*       out     = (float*)d_out;

    int n_neurons = in_sizes[0] / T_STEPS;   // 262144
    int ntiles = n_neurons / ROWS_PER_TILE;  // 4096
    int grid = (ntiles + WARPS_PER_BLOCK - 1) / WARPS_PER_BLOCK;  // 2048

    cudaFuncSetAttribute(lif_kernel,
                         cudaFuncAttributeMaxDynamicSharedMemorySize,
                         (int)SMEM_BYTES);

    lif_kernel<<<grid, BLOCK_THREADS, SMEM_BYTES>>>(x, decay_p, out, n_neurons);
}

// round 17
// speedup vs baseline: 1.0166x; 1.0166x over previous
#include <cuda_runtime.h>
#include <cstdint>

// LIF recurrence — FINAL kernel (roofline-bound, 7-run stable 36.90-37.18us).
// x: [B*N, T] fp32, T=100 contiguous.
//   u_t = decay*u_{t-1} + x_t - o_{t-1}*VTH ; o_t = (u_t - VTH > 0) ? 1 : 0
//
// Wall time is a flat floor set by compulsory DRAM traffic: 105MB read +
// 105MB write per replay at ~5.7TB/s effective mixed-R/W bandwidth
// (~71% of 8TB/s pure-read spec) => ~36.9us. Established by:
//  - 7 architectures (flat LDG, smem-staged, double-buffered pipeline,
//    persistent, warp-specialized TMA ring, block-shared tile) converge
//    at 36.9-41.0us wall while ncu kernel time varies 28-35.5us;
//  - 3 L2-residency mechanisms (TMA cache_hint, st.cs, cp.async
//    cache_hint) all exact no-ops; input not pinnable across replays.
//
// Geometry: per-warp 64-row tile = 25600B contiguous gmem span.
//  Phase 1: whole tile as one cp.async (LDGSTS.128) burst - fully
//           coalesced, 25.6KB in flight per warp.
//  Phase 2: 2 interleaved recurrence chains per thread (rows lane,
//           lane+32), conflict-free LDS.128/STS.128, spikes overwrite
//           input in place.
//  Phase 3: coalesced st.global.cs.v4 streaming stores.
// 2 warps/block, 51.2KB smem, grid 2048 (~3.4 waves on 152 SMs).

#define VTH 0.5f
#define T_STEPS 100
#define T_VEC (T_STEPS / 4)                    // 25
#define ROWS_PER_TILE 64
#define TILE_FLOATS (ROWS_PER_TILE * T_STEPS)  // 6400 floats = 25600 B
#define TILE_VEC (TILE_FLOATS / 4)             // 1600 float4
#define VEC_PER_LANE (TILE_VEC / 32)           // 50
#define WARPS_PER_BLOCK 2
#define BLOCK_THREADS (WARPS_PER_BLOCK * 32)
#define SMEM_BYTES (WARPS_PER_BLOCK * TILE_FLOATS * sizeof(float))  // 51200

__device__ __forceinline__ void cp_async16(uint32_t smem_dst, const void* gmem_src) {
    asm volatile("cp.async.cg.shared.global [%0], [%1], 16;\n"
                 :: "r"(smem_dst), "l"(gmem_src));
}
__device__ __forceinline__ void cp_async_commit() {
    asm volatile("cp.async.commit_group;\n" ::: "memory");
}
__device__ __forceinline__ void cp_async_wait_0() {
    asm volatile("cp.async.wait_group 0;\n" ::: "memory");
}
__device__ __forceinline__ void stg_cs_128(float4* p, float4 v) {
    asm volatile("st.global.cs.v4.f32 [%0], {%1, %2, %3, %4};"
                 :: "l"(p), "f"(v.x), "f"(v.y), "f"(v.z), "f"(v.w) : "memory");
}

#define LIF_STEP(u, o, xv)                      \
    do {                                        \
        u = fmaf(decay, u, xv);                 \
        u = fmaf(-VTH, o, u);                   \
        o = (u > VTH) ? 1.0f : 0.0f;            \
    } while (0)

__global__ void __launch_bounds__(BLOCK_THREADS) lif_kernel(
    const float* __restrict__ x,
    const float* __restrict__ decay_p,
    float* __restrict__ out,
    int n_neurons)
{
    extern __shared__ float smem[];

    const int warp = threadIdx.x >> 5;
    const int lane = threadIdx.x & 31;

    const int ntiles = n_neurons / ROWS_PER_TILE;          // 4096
    const int t = blockIdx.x * WARPS_PER_BLOCK + warp;
    if (t >= ntiles) return;

    const float decay = __ldg(decay_p);

    float* buf = smem + (size_t)warp * TILE_FLOATS;
    uint32_t buf_s = (uint32_t)__cvta_generic_to_shared(buf);

    // ---- Phase 1: whole 25.6KB tile via cp.async, all in flight at once ----
    const float4* g = reinterpret_cast<const float4*>(x + (size_t)t * TILE_FLOATS);
#pragma unroll
    for (int i = 0; i < VEC_PER_LANE; ++i) {
        int idx = lane + 32 * i;                           // coalesced span
        cp_async16(buf_s + (uint32_t)idx * 16u, g + idx);
    }
    cp_async_commit();
    cp_async_wait_0();
    __syncwarp();

    // ---- Phase 2: two interleaved chains per thread (rows lane, lane+32) ----
    {
        float4* r0 = reinterpret_cast<float4*>(buf + (size_t)lane * T_STEPS);
        float4* r1 = reinterpret_cast<float4*>(buf + (size_t)(lane + 32) * T_STEPS);

        float u0 = 0.0f, o0 = 0.0f;
        float u1 = 0.0f, o1 = 0.0f;
#pragma unroll
        for (int q = 0; q < T_VEC; ++q) {
            float4 a = r0[q];
            float4 b = r1[q];
            float4 oa, ob;

            LIF_STEP(u0, o0, a.x);  oa.x = o0;
            LIF_STEP(u1, o1, b.x);  ob.x = o1;
            LIF_STEP(u0, o0, a.y);  oa.y = o0;
            LIF_STEP(u1, o1, b.y);  ob.y = o1;
            LIF_STEP(u0, o0, a.z);  oa.z = o0;
            LIF_STEP(u1, o1, b.z);  ob.z = o1;
            LIF_STEP(u0, o0, a.w);  oa.w = o0;
            LIF_STEP(u1, o1, b.w);  ob.w = o1;

            r0[q] = oa;              // spikes overwrite consumed input
            r1[q] = ob;
        }
    }
    __syncwarp();

    // ---- Phase 3: coalesced streaming stores ----
    {
        const float4* c4 = reinterpret_cast<const float4*>(buf);
        float4* go = reinterpret_cast<float4*>(out + (size_t)t * TILE_FLOATS);
#pragma unroll
        for (int i = 0; i < VEC_PER_LANE; ++i) {
            int idx = lane + 32 * i;
            stg_cs_128(go + idx, c4[idx]);
        }
    }
}

extern "C" void kernel_launch(void* const* d_in, const int* in_sizes, int n_in,
                              void* d_out, int out_size)
{
    const float* x       = (const float*)d_in[0];
    const float* decay_p = (const float*)d_in[1];
    float*       out     = (float*)d_out;

    int n_neurons = in_sizes[0] / T_STEPS;   // 262144
    int ntiles = n_neurons / ROWS_PER_TILE;  // 4096
    int grid = (ntiles + WARPS_PER_BLOCK - 1) / WARPS_PER_BLOCK;  // 2048

    cudaFuncSetAttribute(lif_kernel,
                         cudaFuncAttributeMaxDynamicSharedMemorySize,
                         (int)SMEM_BYTES);

    lif_kernel<<<grid, BLOCK_THREADS, SMEM_BYTES>>>(x, decay_p, out, n_neurons);
}